// round 8
// baseline (speedup 1.0000x reference)
#include <cuda_runtime.h>
#include <cuda_bf16.h>
#include <math.h>
#include <stdint.h>

// ---------------- problem constants ----------------
#define Bb    2
#define Ss    2048
#define MTOK  4096
#define NBATCH 16
#define SCALE 0.08838834764831845f   // 1/sqrt(128)

// ---------------- scratch (device globals; no allocation) ----------------
__device__ float g_cq[MTOK * 128];
__device__ float g_q[MTOK * 1024];
__device__ float g_ckvkr[MTOK * 192];
__device__ float g_ckv[MTOK * 128];
__device__ float g_kr[MTOK * 64];
__device__ float g_kv[MTOK * 2560];
__device__ float g_qs[NBATCH * Ss * 128];
__device__ float g_ks[NBATCH * Ss * 128];
__device__ float g_vt[NBATCH * 256 * Ss];     // V^T per (b,h): [256][2048]
__device__ float g_attn[MTOK * 2048];
// transposed weights [N][K]
__device__ float g_wt_dq[128 * 1024];
__device__ float g_wt_uq[1024 * 128];
__device__ float g_wt_dkv[192 * 1024];
__device__ float g_wt_ukuv[2560 * 128];
__device__ float g_wt_o[1024 * 2048];

// ================= helpers =================
__device__ __forceinline__ uint32_t smem_u32(const void* p) {
    uint32_t a;
    asm("{ .reg .u64 t; cvta.to.shared.u64 t, %1; cvt.u32.u64 %0, t; }" : "=r"(a) : "l"(p));
    return a;
}

#define LDSM4(r0, r1, r2, r3, addr) \
    asm volatile("ldmatrix.sync.aligned.m8n8.x4.shared.b16 {%0,%1,%2,%3}, [%4];" \
                 : "=r"(r0), "=r"(r1), "=r"(r2), "=r"(r3) : "r"(addr))

#define MMA_BF16(d, a, b) \
    asm volatile("mma.sync.aligned.m16n8k16.row.col.f32.bf16.bf16.f32 " \
                 "{%0,%1,%2,%3}, {%4,%5,%6,%7}, {%8,%9}, {%0,%1,%2,%3};" \
                 : "+f"((d)[0]), "+f"((d)[1]), "+f"((d)[2]), "+f"((d)[3]) \
                 : "r"((a)[0]), "r"((a)[1]), "r"((a)[2]), "r"((a)[3]), \
                   "r"((b)[0]), "r"((b)[1]))

__device__ __forceinline__ void split2(float x, float y, uint32_t& hi, uint32_t& lo) {
    __nv_bfloat16 hx = __float2bfloat16(x), hy = __float2bfloat16(y);
    __nv_bfloat16 lx = __float2bfloat16(x - __bfloat162float(hx));
    __nv_bfloat16 ly = __float2bfloat16(y - __bfloat162float(hy));
    __nv_bfloat162 h = __halves2bfloat162(hx, hy);
    __nv_bfloat162 l = __halves2bfloat162(lx, ly);
    hi = *reinterpret_cast<uint32_t*>(&h);
    lo = *reinterpret_cast<uint32_t*>(&l);
}
__device__ __forceinline__ void st2(uint32_t addr, uint32_t a, uint32_t b) {
    asm volatile("st.shared.v2.b32 [%0], {%1,%2};" :: "r"(addr), "r"(a), "r"(b) : "memory");
}
__device__ __forceinline__ void st1(uint32_t addr, uint32_t a) {
    asm volatile("st.shared.b32 [%0], %1;" :: "r"(addr), "r"(a) : "memory");
}

// ================= fused flash attention =================
// One CTA = one 64-row Q block of one (b,h). 256 threads, 8 warps (2m x 4n).
// Q,K [s][128] from g_qs/g_ks; V^T [256][2048] from g_vt; out -> g_attn [B*S][H*256].
#define QROW 136
#define PROW 136
#define KVROW 40
// smem byte offsets
#define OFF_QH 0
#define OFF_QL 17408
#define OFF_PH 34816
#define OFF_PL 52224
#define OFF_KH 69632
#define OFF_KL 79872
#define OFF_VH 90112
#define OFF_VL 110592
#define OFF_R1 131072
#define OFF_R2 132096
#define FLASH_SMEM 133120

__global__ void __launch_bounds__(256)
flash_kernel(const float* __restrict__ qs, const float* __restrict__ ks,
             const float* __restrict__ vt, float* __restrict__ outp)
{
    extern __shared__ char sm[];
    const uint32_t sb = smem_u32(sm);
    const uint32_t uQh = sb + OFF_QH, uQl = sb + OFF_QL;
    const uint32_t uPh = sb + OFF_PH, uPl = sb + OFF_PL;
    const uint32_t uKh = sb + OFF_KH, uKl = sb + OFF_KL;
    const uint32_t uVh = sb + OFF_VH, uVl = sb + OFF_VL;
    float* red1 = reinterpret_cast<float*>(sm + OFF_R1);
    float* red2 = reinterpret_cast<float*>(sm + OFF_R2);

    const int tid = threadIdx.x, lane = tid & 31, wid = tid >> 5;
    const int wm = wid & 1, wn = wid >> 1;
    const int qb = blockIdx.x, bh = blockIdx.y;
    const int b = bh >> 3, head = bh & 7;

    const float* Q = qs + ((long long)bh * Ss + qb * 64) * 128;
    const float* K = ks + (long long)bh * Ss * 128;
    const float* V = vt + (long long)bh * 256 * Ss;

    // ---- load Q (scale folded), split hi/lo ----
#pragma unroll
    for (int p = 0; p < 8; p++) {
        int r = (tid >> 5) + p * 8;         // 0..63
        int c = lane * 4;                    // 0..124
        float4 v = *reinterpret_cast<const float4*>(Q + r * 128 + c);
        v.x *= SCALE; v.y *= SCALE; v.z *= SCALE; v.w *= SCALE;
        uint32_t h0, l0, h1, l1;
        split2(v.x, v.y, h0, l0);
        split2(v.z, v.w, h1, l1);
        uint32_t off = (uint32_t)(r * QROW + c) * 2;
        st2(uQh + off, h0, h1);
        st2(uQl + off, l0, l1);
    }

    float o[2][8][4];
#pragma unroll
    for (int i = 0; i < 2; i++)
#pragma unroll
        for (int j = 0; j < 8; j++)
#pragma unroll
            for (int c = 0; c < 4; c++) o[i][j][c] = 0.f;
    float mr[2][2] = {{-1e30f, -1e30f}, {-1e30f, -1e30f}};
    float lr[2][2] = {{0.f, 0.f}, {0.f, 0.f}};

    for (int kb = 0; kb < 16; kb++) {
        // ================= S = Q @ K^T (64x128) =================
        float s[2][4][4];
#pragma unroll
        for (int i = 0; i < 2; i++)
#pragma unroll
            for (int j = 0; j < 4; j++)
#pragma unroll
                for (int c = 0; c < 4; c++) s[i][j][c] = 0.f;

        for (int ds = 0; ds < 4; ds++) {
            __syncthreads();
            // K slab: 128 keys x 32 d (coalesced: 8 threads per row-segment)
#pragma unroll
            for (int p = 0; p < 4; p++) {
                int r = (tid >> 3) + p * 32;       // key 0..127
                int c = (tid & 7) * 4;             // 0..28
                float4 v = *reinterpret_cast<const float4*>(
                    K + (long long)(kb * 128 + r) * 128 + ds * 32 + c);
                uint32_t h0, l0, h1, l1;
                split2(v.x, v.y, h0, l0);
                split2(v.z, v.w, h1, l1);
                uint32_t off = (uint32_t)(r * KVROW + c) * 2;
                st2(uKh + off, h0, h1);
                st2(uKl + off, l0, l1);
            }
            __syncthreads();
#pragma unroll
            for (int k2 = 0; k2 < 2; k2++) {
                uint32_t bhf[4][2], blf[4][2];
#pragma unroll
                for (int jp = 0; jp < 2; jp++) {
                    int rowb = wn * 32 + jp * 16 + (lane & 7) + ((lane & 16) >> 1);
                    int kc = k2 * 16 + (lane & 8);
                    uint32_t off = (uint32_t)(rowb * KVROW + kc) * 2;
                    LDSM4(bhf[jp * 2][0], bhf[jp * 2][1], bhf[jp * 2 + 1][0], bhf[jp * 2 + 1][1],
                          uKh + off);
                    LDSM4(blf[jp * 2][0], blf[jp * 2][1], blf[jp * 2 + 1][0], blf[jp * 2 + 1][1],
                          uKl + off);
                }
#pragma unroll
                for (int i = 0; i < 2; i++) {
                    int rowa = wm * 32 + i * 16 + (lane & 7) + (lane & 8);
                    int kc = ds * 32 + k2 * 16 + ((lane & 16) >> 1);
                    uint32_t off = (uint32_t)(rowa * QROW + kc) * 2;
                    uint32_t ah[4], al[4];
                    LDSM4(ah[0], ah[1], ah[2], ah[3], uQh + off);
                    LDSM4(al[0], al[1], al[2], al[3], uQl + off);
#pragma unroll
                    for (int j = 0; j < 4; j++) {
                        MMA_BF16(s[i][j], ah, bhf[j]);
                        MMA_BF16(s[i][j], ah, blf[j]);
                        MMA_BF16(s[i][j], al, bhf[j]);
                    }
                }
            }
        }

        // ================= online softmax =================
        float mnew[2][2];
#pragma unroll
        for (int i = 0; i < 2; i++)
#pragma unroll
            for (int hh = 0; hh < 2; hh++) {
                float pm = -1e30f;
#pragma unroll
                for (int j = 0; j < 4; j++)
                    pm = fmaxf(pm, fmaxf(s[i][j][hh * 2], s[i][j][hh * 2 + 1]));
                pm = fmaxf(pm, __shfl_xor_sync(0xffffffffu, pm, 1));
                pm = fmaxf(pm, __shfl_xor_sync(0xffffffffu, pm, 2));
                if ((lane & 3) == 0) {
                    int R = wm * 32 + i * 16 + (lane >> 2) + hh * 8;
                    red1[R * 4 + wn] = pm;
                }
            }
        __syncthreads();
#pragma unroll
        for (int i = 0; i < 2; i++)
#pragma unroll
            for (int hh = 0; hh < 2; hh++) {
                int R = wm * 32 + i * 16 + (lane >> 2) + hh * 8;
                float m4 = fmaxf(fmaxf(red1[R * 4 + 0], red1[R * 4 + 1]),
                                 fmaxf(red1[R * 4 + 2], red1[R * 4 + 3]));
                mnew[i][hh] = fmaxf(mr[i][hh], m4);
            }
        // exp + partial sums
#pragma unroll
        for (int i = 0; i < 2; i++)
#pragma unroll
            for (int hh = 0; hh < 2; hh++) {
                float ps = 0.f;
#pragma unroll
                for (int j = 0; j < 4; j++) {
                    float e0 = __expf(s[i][j][hh * 2]     - mnew[i][hh]);
                    float e1 = __expf(s[i][j][hh * 2 + 1] - mnew[i][hh]);
                    s[i][j][hh * 2]     = e0;
                    s[i][j][hh * 2 + 1] = e1;
                    ps += e0 + e1;
                }
                ps += __shfl_xor_sync(0xffffffffu, ps, 1);
                ps += __shfl_xor_sync(0xffffffffu, ps, 2);
                if ((lane & 3) == 0) {
                    int R = wm * 32 + i * 16 + (lane >> 2) + hh * 8;
                    red2[R * 4 + wn] = ps;
                }
            }
        // rescale O and l by alpha
#pragma unroll
        for (int i = 0; i < 2; i++)
#pragma unroll
            for (int hh = 0; hh < 2; hh++) {
                float alpha = __expf(mr[i][hh] - mnew[i][hh]);
                mr[i][hh] = mnew[i][hh];
                lr[i][hh] *= alpha;
#pragma unroll
                for (int j = 0; j < 8; j++) {
                    o[i][j][hh * 2]     *= alpha;
                    o[i][j][hh * 2 + 1] *= alpha;
                }
            }
        __syncthreads();
#pragma unroll
        for (int i = 0; i < 2; i++)
#pragma unroll
            for (int hh = 0; hh < 2; hh++) {
                int R = wm * 32 + i * 16 + (lane >> 2) + hh * 8;
                lr[i][hh] += red2[R * 4 + 0] + red2[R * 4 + 1] +
                             red2[R * 4 + 2] + red2[R * 4 + 3];
            }
        // store P split hi/lo to smem
#pragma unroll
        for (int i = 0; i < 2; i++) {
            int R0 = wm * 32 + i * 16 + (lane >> 2);
#pragma unroll
            for (int j = 0; j < 4; j++) {
                int C = wn * 32 + j * 8 + (lane & 3) * 2;
                uint32_t hi, lo;
                split2(s[i][j][0], s[i][j][1], hi, lo);
                uint32_t off0 = (uint32_t)(R0 * PROW + C) * 2;
                st1(uPh + off0, hi);
                st1(uPl + off0, lo);
                split2(s[i][j][2], s[i][j][3], hi, lo);
                uint32_t off1 = (uint32_t)((R0 + 8) * PROW + C) * 2;
                st1(uPh + off1, hi);
                st1(uPl + off1, lo);
            }
        }
        __syncthreads();

        // ================= O += P @ V =================
        for (int vs = 0; vs < 4; vs++) {
            // V slab: 256 d-rows x 32 keys
#pragma unroll
            for (int p = 0; p < 8; p++) {
                int r = (tid >> 3) + p * 32;        // d-row 0..255
                int c = (tid & 7) * 4;              // 0..28
                float4 v = *reinterpret_cast<const float4*>(
                    V + (long long)r * Ss + kb * 128 + vs * 32 + c);
                uint32_t h0, l0, h1, l1;
                split2(v.x, v.y, h0, l0);
                split2(v.z, v.w, h1, l1);
                uint32_t off = (uint32_t)(r * KVROW + c) * 2;
                st2(uVh + off, h0, h1);
                st2(uVl + off, l0, l1);
            }
            __syncthreads();
#pragma unroll
            for (int k2 = 0; k2 < 2; k2++) {
                uint32_t vh[8][2], vl[8][2];
#pragma unroll
                for (int jp = 0; jp < 4; jp++) {
                    int rowb = wn * 64 + jp * 16 + (lane & 7) + ((lane & 16) >> 1);
                    int kc = k2 * 16 + (lane & 8);
                    uint32_t off = (uint32_t)(rowb * KVROW + kc) * 2;
                    LDSM4(vh[jp * 2][0], vh[jp * 2][1], vh[jp * 2 + 1][0], vh[jp * 2 + 1][1],
                          uVh + off);
                    LDSM4(vl[jp * 2][0], vl[jp * 2][1], vl[jp * 2 + 1][0], vl[jp * 2 + 1][1],
                          uVl + off);
                }
#pragma unroll
                for (int i = 0; i < 2; i++) {
                    int rowa = wm * 32 + i * 16 + (lane & 7) + (lane & 8);
                    int kc = vs * 32 + k2 * 16 + ((lane & 16) >> 1);
                    uint32_t off = (uint32_t)(rowa * PROW + kc) * 2;
                    uint32_t ph[4], pl[4];
                    LDSM4(ph[0], ph[1], ph[2], ph[3], uPh + off);
                    LDSM4(pl[0], pl[1], pl[2], pl[3], uPl + off);
#pragma unroll
                    for (int j = 0; j < 8; j++) {
                        MMA_BF16(o[i][j], ph, vh[j]);
                        MMA_BF16(o[i][j], ph, vl[j]);
                        MMA_BF16(o[i][j], pl, vh[j]);
                    }
                }
            }
            __syncthreads();
        }
    }

    // ---- epilogue: O/l -> g_attn [B*S][H*256] (permute fused) ----
#pragma unroll
    for (int i = 0; i < 2; i++)
#pragma unroll
        for (int hh = 0; hh < 2; hh++) {
            float inv = 1.f / lr[i][hh];
            int R = wm * 32 + i * 16 + (lane >> 2) + hh * 8;
            long long grow = (long long)b * Ss + qb * 64 + R;
#pragma unroll
            for (int j = 0; j < 8; j++) {
                int col = head * 256 + wn * 64 + j * 8 + (lane & 3) * 2;
                float2 v = make_float2(o[i][j][hh * 2] * inv, o[i][j][hh * 2 + 1] * inv);
                *reinterpret_cast<float2*>(outp + grow * 2048 + col) = v;
            }
        }
}

// ================= warp-MMA split-bf16 GEMM (validated R6) =================
#define SROW 40

__global__ void __launch_bounds__(256)
hgemm_kernel(const float* __restrict__ A, int lda, long long sA,
             const float* __restrict__ Bt, int ldb, long long sB,
             const float* __restrict__ bias,
             float* __restrict__ C, int ldc, long long sC,
             int N, int K, float alpha)
{
    __shared__ __align__(16) __nv_bfloat16 sAh[128 * SROW];
    __shared__ __align__(16) __nv_bfloat16 sAl[128 * SROW];
    __shared__ __align__(16) __nv_bfloat16 sBh[128 * SROW];
    __shared__ __align__(16) __nv_bfloat16 sBl[128 * SROW];

    const int tid  = threadIdx.x;
    const int lane = tid & 31;
    const int wid  = tid >> 5;
    const int wm   = wid & 1;
    const int wn   = wid >> 1;

    const int z  = blockIdx.z;
    A  += z * sA;
    Bt += z * sB;
    C  += z * sC;
    const int m0 = blockIdx.y * 128;
    const int n0 = blockIdx.x * 128;

    const uint32_t uAh = smem_u32(sAh), uAl = smem_u32(sAl);
    const uint32_t uBh = smem_u32(sBh), uBl = smem_u32(sBl);

    const int lr  = tid >> 2;
    const int lc4 = (tid & 3) * 2;

    float4 pa[4], pb[4];
    float acc[4][4][4];
#pragma unroll
    for (int i = 0; i < 4; i++)
#pragma unroll
        for (int j = 0; j < 4; j++)
#pragma unroll
            for (int c = 0; c < 4; c++) acc[i][j][c] = 0.f;

#pragma unroll
    for (int u = 0; u < 4; u++) {
        int r  = lr + (u >> 1) * 64;
        int c4 = lc4 + (u & 1);
        pa[u] = *reinterpret_cast<const float4*>(A + (long long)(m0 + r) * lda + c4 * 4);
        int bn = n0 + r;
        pb[u] = (bn < N)
            ? *reinterpret_cast<const float4*>(Bt + (long long)bn * ldb + c4 * 4)
            : make_float4(0.f, 0.f, 0.f, 0.f);
    }

    const int nk = K >> 5;
    for (int s = 0; s < nk; s++) {
#pragma unroll
        for (int u = 0; u < 4; u++) {
            int r = lr + (u >> 1) * 64;
            int c = (lc4 + (u & 1)) * 4;
            uint32_t h0, l0, h1, l1;
            split2(pa[u].x, pa[u].y, h0, l0);
            split2(pa[u].z, pa[u].w, h1, l1);
            *reinterpret_cast<uint32_t*>(&sAh[r * SROW + c])     = h0;
            *reinterpret_cast<uint32_t*>(&sAh[r * SROW + c + 2]) = h1;
            *reinterpret_cast<uint32_t*>(&sAl[r * SROW + c])     = l0;
            *reinterpret_cast<uint32_t*>(&sAl[r * SROW + c + 2]) = l1;
            split2(pb[u].x, pb[u].y, h0, l0);
            split2(pb[u].z, pb[u].w, h1, l1);
            *reinterpret_cast<uint32_t*>(&sBh[r * SROW + c])     = h0;
            *reinterpret_cast<uint32_t*>(&sBh[r * SROW + c + 2]) = h1;
            *reinterpret_cast<uint32_t*>(&sBl[r * SROW + c])     = l0;
            *reinterpret_cast<uint32_t*>(&sBl[r * SROW + c + 2]) = l1;
        }
        __syncthreads();

        if (s + 1 < nk) {
            const int kt = (s + 1) << 5;
#pragma unroll
            for (int u = 0; u < 4; u++) {
                int r  = lr + (u >> 1) * 64;
                int c4 = lc4 + (u & 1);
                pa[u] = *reinterpret_cast<const float4*>(
                    A + (long long)(m0 + r) * lda + kt + c4 * 4);
                int bn = n0 + r;
                pb[u] = (bn < N)
                    ? *reinterpret_cast<const float4*>(
                          Bt + (long long)bn * ldb + kt + c4 * 4)
                    : make_float4(0.f, 0.f, 0.f, 0.f);
            }
        }

#pragma unroll
        for (int ks = 0; ks < 2; ks++) {
            uint32_t bh[4][2], bl[4][2];
#pragma unroll
            for (int jp = 0; jp < 2; jp++) {
                int rowb = wn * 32 + jp * 16 + (lane & 7) + ((lane & 16) >> 1);
                int kc   = ks * 16 + (lane & 8);
                uint32_t off = (uint32_t)(rowb * SROW + kc) * 2;
                LDSM4(bh[jp * 2][0], bh[jp * 2][1], bh[jp * 2 + 1][0], bh[jp * 2 + 1][1],
                      uBh + off);
                LDSM4(bl[jp * 2][0], bl[jp * 2][1], bl[jp * 2 + 1][0], bl[jp * 2 + 1][1],
                      uBl + off);
            }
#pragma unroll
            for (int i = 0; i < 4; i++) {
                int rowa = wm * 64 + i * 16 + (lane & 7) + (lane & 8);
                int kc   = ks * 16 + ((lane & 16) >> 1);
                uint32_t off = (uint32_t)(rowa * SROW + kc) * 2;
                uint32_t ah[4], al[4];
                LDSM4(ah[0], ah[1], ah[2], ah[3], uAh + off);
                LDSM4(al[0], al[1], al[2], al[3], uAl + off);
#pragma unroll
                for (int j = 0; j < 4; j++) {
                    MMA_BF16(acc[i][j], ah, bh[j]);
                    MMA_BF16(acc[i][j], ah, bl[j]);
                    MMA_BF16(acc[i][j], al, bh[j]);
                }
            }
        }
        __syncthreads();
    }

#pragma unroll
    for (int j = 0; j < 4; j++) {
        int col = n0 + wn * 32 + j * 8 + (lane & 3) * 2;
        if (col >= N) continue;
        float b0 = 0.f, b1 = 0.f;
        if (bias) { b0 = bias[col]; b1 = bias[col + 1]; }
#pragma unroll
        for (int i = 0; i < 4; i++) {
            int row = m0 + wm * 64 + i * 16 + (lane >> 2);
            float2 v0 = make_float2(acc[i][j][0] * alpha + b0,
                                    acc[i][j][1] * alpha + b1);
            float2 v1 = make_float2(acc[i][j][2] * alpha + b0,
                                    acc[i][j][3] * alpha + b1);
            *reinterpret_cast<float2*>(C + (long long)row * ldc + col)       = v0;
            *reinterpret_cast<float2*>(C + (long long)(row + 8) * ldc + col) = v1;
        }
    }
}

// ================= transpose kernels =================
__global__ void transpose_kernel(const float* __restrict__ src, int R, int Cc,
                                 float* __restrict__ dst)
{
    __shared__ float t[32][33];
    int r0 = blockIdx.y * 32, c0 = blockIdx.x * 32;
    int tx = threadIdx.x, ty = threadIdx.y;
#pragma unroll
    for (int i = 0; i < 32; i += 8)
        if (r0 + ty + i < R && c0 + tx < Cc)
            t[ty + i][tx] = src[(long long)(r0 + ty + i) * Cc + c0 + tx];
    __syncthreads();
#pragma unroll
    for (int i = 0; i < 32; i += 8)
        if (c0 + ty + i < Cc && r0 + tx < R)
            dst[(long long)(c0 + ty + i) * R + r0 + tx] = t[tx][ty + i];
}

__global__ void build_vT_kernel(const float* __restrict__ kv, float* __restrict__ vt)
{
    __shared__ float t[32][33];
    int z = blockIdx.z, b = z >> 3, h = z & 7;
    const float* src = kv + (long long)b * 2048 * 2560 + 512 + h * 256;
    float* dst = vt + (long long)z * 256 * 2048;
    int s0 = blockIdx.x * 32, d0 = blockIdx.y * 32;
    int tx = threadIdx.x, ty = threadIdx.y;
#pragma unroll
    for (int i = 0; i < 32; i += 8)
        t[ty + i][tx] = src[(long long)(s0 + ty + i) * 2560 + d0 + tx];
    __syncthreads();
#pragma unroll
    for (int i = 0; i < 32; i += 8)
        dst[(long long)(d0 + ty + i) * 2048 + s0 + tx] = t[tx][ty + i];
}

// ================= elementwise kernels =================
__global__ void rmsnorm128_kernel(float* __restrict__ buf, const float* __restrict__ w)
{
    int row = blockIdx.x, tid = threadIdx.x;
    float v = buf[row * 128 + tid];
    float ss = v * v;
#pragma unroll
    for (int o = 16; o; o >>= 1) ss += __shfl_xor_sync(0xffffffffu, ss, o);
    __shared__ float red[4];
    if ((tid & 31) == 0) red[tid >> 5] = ss;
    __syncthreads();
    float tot = red[0] + red[1] + red[2] + red[3];
    float rs = rsqrtf(tot * (1.f / 128.f) + 1e-8f);
    buf[row * 128 + tid] = w[tid] * v * rs;
}

__global__ void post_ckvkr_kernel(const float* __restrict__ in,
                                  const float* __restrict__ w,
                                  const int* __restrict__ pos,
                                  float* __restrict__ ckv,
                                  float* __restrict__ kr)
{
    int row = blockIdx.x, tid = threadIdx.x;
    float v = in[row * 192 + tid];
    float ss = v * v;
#pragma unroll
    for (int o = 16; o; o >>= 1) ss += __shfl_xor_sync(0xffffffffu, ss, o);
    __shared__ float red[4];
    if ((tid & 31) == 0) red[tid >> 5] = ss;
    __syncthreads();
    float tot = red[0] + red[1] + red[2] + red[3];
    float rs = rsqrtf(tot * (1.f / 128.f) + 1e-8f);
    ckv[row * 128 + tid] = w[tid] * v * rs;

    if (tid < 32) {
        float xe = in[row * 192 + 128 + 2 * tid];
        float xo = in[row * 192 + 128 + 2 * tid + 1];
        float invf = powf(10000.f, -(float)(2 * tid) / 64.f);
        float ang = (float)pos[row] * invf;
        float s, c;
        sincosf(ang, &s, &c);
        kr[row * 64 + 2 * tid]     = xe * c - xo * s;
        kr[row * 64 + 2 * tid + 1] = xe * s + xo * c;
    }
}

__global__ void build_q_kernel(const float* __restrict__ q,
                               const int* __restrict__ pos,
                               float* __restrict__ qs)
{
    int idx = blockIdx.x * blockDim.x + threadIdx.x;
    int d = idx & 127;
    int t = idx >> 7;
    int qp = t & (Ss - 1);
    int zz = t >> 11;
    int b = zz >> 3, h = zz & 7;
    int row = b * Ss + qp;
    float val;
    if (d < 96) {
        val = q[row * 1024 + h * 96 + d];
    } else {
        int r = d - 96;
        int i = r >> 1;
        float xe = q[row * 1024 + 768 + h * 32 + 2 * i];
        float xo = q[row * 1024 + 768 + h * 32 + 2 * i + 1];
        float invf = powf(10000.f, -(float)(2 * i) / 32.f);
        float ang = (float)pos[row] * invf;
        float s, c;
        sincosf(ang, &s, &c);
        val = (r & 1) ? (xe * s + xo * c) : (xe * c - xo * s);
    }
    qs[idx] = val;
}

__global__ void build_k_kernel(const float* __restrict__ kv,
                               const float* __restrict__ kr,
                               float* __restrict__ ks)
{
    int idx = blockIdx.x * blockDim.x + threadIdx.x;
    int d = idx & 127;
    int t = idx >> 7;
    int qp = t & (Ss - 1);
    int zz = t >> 11;
    int b = zz >> 3, h = zz & 7;
    int row = b * Ss + qp;
    ks[idx] = (d < 64) ? kv[row * 2560 + h * 64 + d] : kr[row * 64 + (d - 64)];
}

// ================= launch =================
extern "C" void kernel_launch(void* const* d_in, const int* in_sizes, int n_in,
                              void* d_out, int out_size)
{
    const float* x         = (const float*)d_in[0];
    const int*   pos       = (const int*)  d_in[1];
    const float* w_dq_w    = (const float*)d_in[2];
    const float* w_dq_b    = (const float*)d_in[3];
    const float* q_norm_w  = (const float*)d_in[4];
    const float* w_uq_qr_w = (const float*)d_in[5];
    const float* w_uq_qr_b = (const float*)d_in[6];
    const float* w_dkv_w   = (const float*)d_in[7];
    const float* w_dkv_b   = (const float*)d_in[8];
    const float* kv_norm_w = (const float*)d_in[9];
    const float* w_ukuv_w  = (const float*)d_in[10];
    const float* w_ukuv_b  = (const float*)d_in[11];
    const float* w_o_w     = (const float*)d_in[12];
    const float* w_o_b     = (const float*)d_in[13];
    float* out = (float*)d_out;

    float *p_cq, *p_q, *p_ckvkr, *p_ckv, *p_kr, *p_kv;
    float *p_qs, *p_ks, *p_vt, *p_attn;
    float *pt_dq, *pt_uq, *pt_dkv, *pt_ukuv, *pt_o;
    cudaGetSymbolAddress((void**)&p_cq,    g_cq);
    cudaGetSymbolAddress((void**)&p_q,     g_q);
    cudaGetSymbolAddress((void**)&p_ckvkr, g_ckvkr);
    cudaGetSymbolAddress((void**)&p_ckv,   g_ckv);
    cudaGetSymbolAddress((void**)&p_kr,    g_kr);
    cudaGetSymbolAddress((void**)&p_kv,    g_kv);
    cudaGetSymbolAddress((void**)&p_qs,    g_qs);
    cudaGetSymbolAddress((void**)&p_ks,    g_ks);
    cudaGetSymbolAddress((void**)&p_vt,    g_vt);
    cudaGetSymbolAddress((void**)&p_attn,  g_attn);
    cudaGetSymbolAddress((void**)&pt_dq,   g_wt_dq);
    cudaGetSymbolAddress((void**)&pt_uq,   g_wt_uq);
    cudaGetSymbolAddress((void**)&pt_dkv,  g_wt_dkv);
    cudaGetSymbolAddress((void**)&pt_ukuv, g_wt_ukuv);
    cudaGetSymbolAddress((void**)&pt_o,    g_wt_o);

    cudaFuncSetAttribute(flash_kernel, cudaFuncAttributeMaxDynamicSharedMemorySize,
                         FLASH_SMEM);

    dim3 tb(32, 8);

    // ---- weight transposes ----
    transpose_kernel<<<dim3(128 / 32, 1024 / 32), tb>>>(w_dq_w,    1024, 128,  pt_dq);
    transpose_kernel<<<dim3(1024 / 32, 128 / 32), tb>>>(w_uq_qr_w, 128, 1024,  pt_uq);
    transpose_kernel<<<dim3(192 / 32, 1024 / 32), tb>>>(w_dkv_w,   1024, 192,  pt_dkv);
    transpose_kernel<<<dim3(2560 / 32, 128 / 32), tb>>>(w_ukuv_w,  128, 2560,  pt_ukuv);
    transpose_kernel<<<dim3(1024 / 32, 2048 / 32), tb>>>(w_o_w,    2048, 1024, pt_o);

    // 1) cq = x @ w_dq + b
    hgemm_kernel<<<dim3(1, 32, 1), 256>>>(
        x, 1024, 0, pt_dq, 1024, 0, w_dq_b, p_cq, 128, 0, 128, 1024, 1.f);
    // 2) rmsnorm
    rmsnorm128_kernel<<<MTOK, 128>>>(p_cq, q_norm_w);
    // 3) q = cq @ w_uq + b
    hgemm_kernel<<<dim3(8, 32, 1), 256>>>(
        p_cq, 128, 0, pt_uq, 128, 0, w_uq_qr_b, p_q, 1024, 0, 1024, 128, 1.f);
    // 4) ckv_kr = x @ w_dkv + b
    hgemm_kernel<<<dim3(2, 32, 1), 256>>>(
        x, 1024, 0, pt_dkv, 1024, 0, w_dkv_b, p_ckvkr, 192, 0, 192, 1024, 1.f);
    // 5) rmsnorm(ckv) + rope(k_rope)
    post_ckvkr_kernel<<<MTOK, 128>>>(p_ckvkr, kv_norm_w, pos, p_ckv, p_kr);
    // 6) kv = ckv @ w_ukuv + b
    hgemm_kernel<<<dim3(20, 32, 1), 256>>>(
        p_ckv, 128, 0, pt_ukuv, 128, 0, w_ukuv_b, p_kv, 2560, 0, 2560, 128, 1.f);
    // 7) build q/k states and V^T
    build_q_kernel<<<(NBATCH * Ss * 128) / 256, 256>>>(p_q, pos, p_qs);
    build_k_kernel<<<(NBATCH * Ss * 128) / 256, 256>>>(p_kv, p_kr, p_ks);
    build_vT_kernel<<<dim3(2048 / 32, 256 / 32, NBATCH), tb>>>(p_kv, p_vt);
    // 8) fused flash attention -> g_attn [B*S][H*256]
    flash_kernel<<<dim3(32, 16), 256, FLASH_SMEM>>>(p_qs, p_ks, p_vt, p_attn);
    // 9) out = attn @ w_o + b
    hgemm_kernel<<<dim3(8, 32, 1), 256>>>(
        p_attn, 2048, 0, pt_o, 2048, 0, w_o_b, out, 1024, 0, 1024, 2048, 1.f);
}

// round 10
// speedup vs baseline: 1.3144x; 1.3144x over previous
#include <cuda_runtime.h>
#include <cuda_bf16.h>
#include <math.h>
#include <stdint.h>

// ---------------- problem constants ----------------
#define Bb    2
#define Ss    2048
#define MTOK  4096
#define NBATCH 16
#define SCALE 0.08838834764831845f   // 1/sqrt(128)

// ---------------- scratch (device globals; no allocation) ----------------
__device__ float g_cq[MTOK * 128];
__device__ float g_q[MTOK * 1024];
__device__ float g_ckvkr[MTOK * 192];
__device__ float g_ckv[MTOK * 128];
__device__ float g_kr[MTOK * 64];
__device__ float g_kv[MTOK * 2560];
__device__ float g_qs[NBATCH * Ss * 128];
__device__ float g_sc[(long long)NBATCH * Ss * Ss];   // 268 MB
__device__ float g_attn[MTOK * 2048];
// pre-split bf16 B operands (hi/lo)
__device__ __nv_bfloat16 g_ks_h[NBATCH * Ss * 128];
__device__ __nv_bfloat16 g_ks_l[NBATCH * Ss * 128];
__device__ __nv_bfloat16 g_vt_h[NBATCH * 256 * Ss];
__device__ __nv_bfloat16 g_vt_l[NBATCH * 256 * Ss];
__device__ __nv_bfloat16 g_wdq_h[128 * 1024],  g_wdq_l[128 * 1024];
__device__ __nv_bfloat16 g_wuq_h[1024 * 128],  g_wuq_l[1024 * 128];
__device__ __nv_bfloat16 g_wdkv_h[192 * 1024], g_wdkv_l[192 * 1024];
__device__ __nv_bfloat16 g_wukuv_h[2560 * 128], g_wukuv_l[2560 * 128];
__device__ __nv_bfloat16 g_wo_h[1024 * 2048],  g_wo_l[1024 * 2048];

// ================= helpers =================
__device__ __forceinline__ uint32_t smem_u32(const void* p) {
    uint32_t a;
    asm("{ .reg .u64 t; cvta.to.shared.u64 t, %1; cvt.u32.u64 %0, t; }" : "=r"(a) : "l"(p));
    return a;
}

#define LDSM4(r0, r1, r2, r3, addr) \
    asm volatile("ldmatrix.sync.aligned.m8n8.x4.shared.b16 {%0,%1,%2,%3}, [%4];" \
                 : "=r"(r0), "=r"(r1), "=r"(r2), "=r"(r3) : "r"(addr))

#define MMA_BF16(d, a, b) \
    asm volatile("mma.sync.aligned.m16n8k16.row.col.f32.bf16.bf16.f32 " \
                 "{%0,%1,%2,%3}, {%4,%5,%6,%7}, {%8,%9}, {%0,%1,%2,%3};" \
                 : "+f"((d)[0]), "+f"((d)[1]), "+f"((d)[2]), "+f"((d)[3]) \
                 : "r"((a)[0]), "r"((a)[1]), "r"((a)[2]), "r"((a)[3]), \
                   "r"((b)[0]), "r"((b)[1]))

__device__ __forceinline__ void split2(float x, float y, uint32_t& hi, uint32_t& lo) {
    __nv_bfloat16 hx = __float2bfloat16(x), hy = __float2bfloat16(y);
    __nv_bfloat16 lx = __float2bfloat16(x - __bfloat162float(hx));
    __nv_bfloat16 ly = __float2bfloat16(y - __bfloat162float(hy));
    __nv_bfloat162 h = __halves2bfloat162(hx, hy);
    __nv_bfloat162 l = __halves2bfloat162(lx, ly);
    hi = *reinterpret_cast<uint32_t*>(&h);
    lo = *reinterpret_cast<uint32_t*>(&l);
}
__device__ __forceinline__ void cpa16(uint32_t dst, const void* src) {
    asm volatile("cp.async.cg.shared.global [%0], [%1], 16;" :: "r"(dst), "l"(src));
}
#define CP_COMMIT() asm volatile("cp.async.commit_group;" ::: "memory")
#define CP_WAIT0()  asm volatile("cp.async.wait_group 0;" ::: "memory")

// ================= double-buffered split-bf16 GEMM =================
// C[m,n] = alpha * sum_k A[m,k]*B[n,k] + bias[n]
// A fp32 (split in-kernel), B pre-split bf16 hi/lo (cp.async).
// Block 128x128, BK=32, 256 threads (8 warps 2m x 4n). M%128==0, K%32==0.
#define SROW 40                       // bf16 elems per smem row (80 B = 5*16B)
#define TILE_B ((uint32_t)(128 * SROW * 2))   // 10240 bytes per matrix tile
#define STAGE_B (4 * TILE_B)                  // Ah, Al, Bh, Bl
#define GEMM_SMEM (2 * STAGE_B)               // 81920

template <int PERMZ>
__global__ void __launch_bounds__(256)
hgemm2_kernel(const float* __restrict__ A, int lda, long long sA,
              const __nv_bfloat16* __restrict__ Bh,
              const __nv_bfloat16* __restrict__ Bl, int ldb, long long sB,
              const float* __restrict__ bias,
              float* __restrict__ C, int ldc, long long sC,
              int N, int K, float alpha)
{
    extern __shared__ char smraw[];
    const uint32_t sb = smem_u32(smraw);

    const int tid  = threadIdx.x;
    const int lane = tid & 31;
    const int wid  = tid >> 5;
    const int wm   = wid & 1;
    const int wn   = wid >> 1;

    const int z  = blockIdx.z;
    A  += z * sA;
    Bh += z * sB;
    Bl += z * sB;
    const int m0 = blockIdx.y * 128;
    const int n0 = blockIdx.x * 128;

    // loader mapping (A): rows {lr, lr+64}, float4 cols {lc4, lc4+1}
    const int lr  = tid >> 2;
    const int lc4 = (tid & 3) * 2;
    float4 pa[4];

    float acc[4][4][4];
#pragma unroll
    for (int i = 0; i < 4; i++)
#pragma unroll
        for (int j = 0; j < 4; j++)
#pragma unroll
            for (int c = 0; c < 4; c++) acc[i][j][c] = 0.f;

    // ---- helpers as macros over buffer base ----
#define BUF_AH(t) (sb + (t) * STAGE_B)
#define BUF_AL(t) (sb + (t) * STAGE_B + TILE_B)
#define BUF_BH(t) (sb + (t) * STAGE_B + 2 * TILE_B)
#define BUF_BL(t) (sb + (t) * STAGE_B + 3 * TILE_B)

#define PREFETCH_A(kt)                                                          \
    {                                                                           \
        _Pragma("unroll")                                                       \
        for (int u = 0; u < 4; u++) {                                           \
            int r  = lr + (u >> 1) * 64;                                        \
            int c4 = lc4 + (u & 1);                                             \
            pa[u] = *reinterpret_cast<const float4*>(                           \
                A + (long long)(m0 + r) * lda + (kt) + c4 * 4);                 \
        }                                                                       \
    }

#define STORE_A(t)                                                              \
    {                                                                           \
        _Pragma("unroll")                                                       \
        for (int u = 0; u < 4; u++) {                                           \
            int r = lr + (u >> 1) * 64;                                         \
            int c = (lc4 + (u & 1)) * 4;                                        \
            uint32_t h0, l0, h1, l1;                                            \
            split2(pa[u].x, pa[u].y, h0, l0);                                   \
            split2(pa[u].z, pa[u].w, h1, l1);                                   \
            uint32_t off = (uint32_t)(r * SROW + c) * 2;                        \
            asm volatile("st.shared.v2.b32 [%0], {%1,%2};" ::                   \
                         "r"(BUF_AH(t) + off), "r"(h0), "r"(h1) : "memory");    \
            asm volatile("st.shared.v2.b32 [%0], {%1,%2};" ::                   \
                         "r"(BUF_AL(t) + off), "r"(l0), "r"(l1) : "memory");    \
        }                                                                       \
    }

#define LOAD_B(kt, t)                                                           \
    {                                                                           \
        _Pragma("unroll")                                                       \
        for (int u = 0; u < 2; u++) {                                           \
            int id = tid * 2 + u;                                               \
            int r  = id >> 2;                                                   \
            int cc = (id & 3) * 8;                                              \
            uint32_t doff = (uint32_t)(r * SROW + cc) * 2;                      \
            int gn = n0 + r;                                                    \
            if (gn < N) {                                                       \
                cpa16(BUF_BH(t) + doff, Bh + (long long)gn * ldb + (kt) + cc);  \
                cpa16(BUF_BL(t) + doff, Bl + (long long)gn * ldb + (kt) + cc);  \
            } else {                                                            \
                asm volatile("st.shared.v4.b32 [%0], {%1,%1,%1,%1};" ::         \
                             "r"(BUF_BH(t) + doff), "r"(0) : "memory");         \
                asm volatile("st.shared.v4.b32 [%0], {%1,%1,%1,%1};" ::         \
                             "r"(BUF_BL(t) + doff), "r"(0) : "memory");         \
            }                                                                   \
        }                                                                       \
    }

    // ---- prologue: stage 0 ----
    PREFETCH_A(0);
    LOAD_B(0, 0);
    CP_COMMIT();
    STORE_A(0);
    CP_WAIT0();
    __syncthreads();

    const int nk = K >> 5;
    for (int s = 0; s < nk; s++) {
        const int cur = s & 1, nxt = cur ^ 1;
        if (s + 1 < nk) {
            PREFETCH_A((s + 1) << 5);
            LOAD_B((s + 1) << 5, nxt);
            CP_COMMIT();
        }

        // ---- compute from buffer cur: 2 k16 substeps ----
        const uint32_t uAh = BUF_AH(cur), uAl = BUF_AL(cur);
        const uint32_t uBh = BUF_BH(cur), uBl = BUF_BL(cur);
#pragma unroll
        for (int ks = 0; ks < 2; ks++) {
            uint32_t bh[4][2], bl[4][2];
#pragma unroll
            for (int jp = 0; jp < 2; jp++) {
                int rowb = wn * 32 + jp * 16 + (lane & 7) + ((lane & 16) >> 1);
                int kc   = ks * 16 + (lane & 8);
                uint32_t off = (uint32_t)(rowb * SROW + kc) * 2;
                LDSM4(bh[jp * 2][0], bh[jp * 2][1], bh[jp * 2 + 1][0], bh[jp * 2 + 1][1],
                      uBh + off);
                LDSM4(bl[jp * 2][0], bl[jp * 2][1], bl[jp * 2 + 1][0], bl[jp * 2 + 1][1],
                      uBl + off);
            }
#pragma unroll
            for (int i = 0; i < 4; i++) {
                int rowa = wm * 64 + i * 16 + (lane & 7) + (lane & 8);
                int kc   = ks * 16 + ((lane & 16) >> 1);
                uint32_t off = (uint32_t)(rowa * SROW + kc) * 2;
                uint32_t ah[4], al[4];
                LDSM4(ah[0], ah[1], ah[2], ah[3], uAh + off);
                LDSM4(al[0], al[1], al[2], al[3], uAl + off);
#pragma unroll
                for (int j = 0; j < 4; j++) {
                    MMA_BF16(acc[i][j], ah, bh[j]);
                    MMA_BF16(acc[i][j], ah, bl[j]);
                    MMA_BF16(acc[i][j], al, bh[j]);
                }
            }
        }

        if (s + 1 < nk) {
            STORE_A(nxt);
            CP_WAIT0();
        }
        __syncthreads();
    }

    // ---- epilogue ----
    float* Cp;
    int ldcc;
    if (PERMZ) {
        // z = b*8 + h ; out[b*Ss + m][h*256 + n], N=256
        Cp = C + ((long long)(z >> 3) * Ss) * 2048 + (z & 7) * 256;
        ldcc = 2048;
    } else {
        Cp = C + z * sC;
        ldcc = ldc;
    }
#pragma unroll
    for (int j = 0; j < 4; j++) {
        int col = n0 + wn * 32 + j * 8 + (lane & 3) * 2;
        if (col >= N) continue;
        float b0 = 0.f, b1 = 0.f;
        if (bias) { b0 = bias[col]; b1 = bias[col + 1]; }
#pragma unroll
        for (int i = 0; i < 4; i++) {
            int row = m0 + wm * 64 + i * 16 + (lane >> 2);
            float2 v0 = make_float2(acc[i][j][0] * alpha + b0,
                                    acc[i][j][1] * alpha + b1);
            float2 v1 = make_float2(acc[i][j][2] * alpha + b0,
                                    acc[i][j][3] * alpha + b1);
            *reinterpret_cast<float2*>(Cp + (long long)row * ldcc + col)       = v0;
            *reinterpret_cast<float2*>(Cp + (long long)(row + 8) * ldcc + col) = v1;
        }
    }
#undef BUF_AH
#undef BUF_AL
#undef BUF_BH
#undef BUF_BL
#undef PREFETCH_A
#undef STORE_A
#undef LOAD_B
}

// ================= transpose + split: fp32 [R][C] -> bf16 hi/lo [C][R] =====
__global__ void transpose_split_kernel(const float* __restrict__ src, int R, int Cc,
                                       __nv_bfloat16* __restrict__ dh,
                                       __nv_bfloat16* __restrict__ dl)
{
    __shared__ float t[32][33];
    int r0 = blockIdx.y * 32, c0 = blockIdx.x * 32;
    int tx = threadIdx.x, ty = threadIdx.y;    // 32 x 8
#pragma unroll
    for (int i = 0; i < 32; i += 8)
        if (r0 + ty + i < R && c0 + tx < Cc)
            t[ty + i][tx] = src[(long long)(r0 + ty + i) * Cc + c0 + tx];
    __syncthreads();
#pragma unroll
    for (int i = 0; i < 32; i += 8)
        if (c0 + ty + i < Cc && r0 + tx < R) {
            float v = t[tx][ty + i];
            __nv_bfloat16 h = __float2bfloat16(v);
            long long o = (long long)(c0 + ty + i) * R + r0 + tx;
            dh[o] = h;
            dl[o] = __float2bfloat16(v - __bfloat162float(h));
        }
}

// V^T split: vt[z][d][s] from kv[(b*2048+s)*2560 + 512 + h*256 + d]
__global__ void build_vT_split_kernel(const float* __restrict__ kv,
                                      __nv_bfloat16* __restrict__ vh,
                                      __nv_bfloat16* __restrict__ vl)
{
    __shared__ float t[32][33];
    int z = blockIdx.z, b = z >> 3, h = z & 7;
    const float* src = kv + (long long)b * 2048 * 2560 + 512 + h * 256;
    long long dbase = (long long)z * 256 * 2048;
    int s0 = blockIdx.x * 32, d0 = blockIdx.y * 32;
    int tx = threadIdx.x, ty = threadIdx.y;
#pragma unroll
    for (int i = 0; i < 32; i += 8)
        t[ty + i][tx] = src[(long long)(s0 + ty + i) * 2560 + d0 + tx];
    __syncthreads();
#pragma unroll
    for (int i = 0; i < 32; i += 8) {
        float v = t[tx][ty + i];
        __nv_bfloat16 hh = __float2bfloat16(v);
        long long o = dbase + (long long)(d0 + ty + i) * 2048 + s0 + tx;
        vh[o] = hh;
        vl[o] = __float2bfloat16(v - __bfloat162float(hh));
    }
}

// ================= elementwise kernels =================
__global__ void rmsnorm128_kernel(float* __restrict__ buf, const float* __restrict__ w)
{
    int row = blockIdx.x, tid = threadIdx.x;
    float v = buf[row * 128 + tid];
    float ss = v * v;
#pragma unroll
    for (int o = 16; o; o >>= 1) ss += __shfl_xor_sync(0xffffffffu, ss, o);
    __shared__ float red[4];
    if ((tid & 31) == 0) red[tid >> 5] = ss;
    __syncthreads();
    float tot = red[0] + red[1] + red[2] + red[3];
    float rs = rsqrtf(tot * (1.f / 128.f) + 1e-8f);
    buf[row * 128 + tid] = w[tid] * v * rs;
}

__global__ void post_ckvkr_kernel(const float* __restrict__ in,
                                  const float* __restrict__ w,
                                  const int* __restrict__ pos,
                                  float* __restrict__ ckv,
                                  float* __restrict__ kr)
{
    int row = blockIdx.x, tid = threadIdx.x;
    float v = in[row * 192 + tid];
    float ss = v * v;
#pragma unroll
    for (int o = 16; o; o >>= 1) ss += __shfl_xor_sync(0xffffffffu, ss, o);
    __shared__ float red[4];
    if ((tid & 31) == 0) red[tid >> 5] = ss;
    __syncthreads();
    float tot = red[0] + red[1] + red[2] + red[3];
    float rs = rsqrtf(tot * (1.f / 128.f) + 1e-8f);
    ckv[row * 128 + tid] = w[tid] * v * rs;

    if (tid < 32) {
        float xe = in[row * 192 + 128 + 2 * tid];
        float xo = in[row * 192 + 128 + 2 * tid + 1];
        float invf = powf(10000.f, -(float)(2 * tid) / 64.f);
        float ang = (float)pos[row] * invf;
        float s, c;
        sincosf(ang, &s, &c);
        kr[row * 64 + 2 * tid]     = xe * c - xo * s;
        kr[row * 64 + 2 * tid + 1] = xe * s + xo * c;
    }
}

__global__ void build_q_kernel(const float* __restrict__ q,
                               const int* __restrict__ pos,
                               float* __restrict__ qs)
{
    int idx = blockIdx.x * blockDim.x + threadIdx.x;
    int d = idx & 127;
    int t = idx >> 7;
    int qp = t & (Ss - 1);
    int zz = t >> 11;
    int b = zz >> 3, h = zz & 7;
    int row = b * Ss + qp;
    float val;
    if (d < 96) {
        val = q[row * 1024 + h * 96 + d];
    } else {
        int r = d - 96;
        int i = r >> 1;
        float xe = q[row * 1024 + 768 + h * 32 + 2 * i];
        float xo = q[row * 1024 + 768 + h * 32 + 2 * i + 1];
        float invf = powf(10000.f, -(float)(2 * i) / 32.f);
        float ang = (float)pos[row] * invf;
        float s, c;
        sincosf(ang, &s, &c);
        val = (r & 1) ? (xe * s + xo * c) : (xe * c - xo * s);
    }
    qs[idx] = val;
}

__global__ void build_k_split_kernel(const float* __restrict__ kv,
                                     const float* __restrict__ kr,
                                     __nv_bfloat16* __restrict__ kh,
                                     __nv_bfloat16* __restrict__ kl)
{
    int idx = blockIdx.x * blockDim.x + threadIdx.x;
    int d = idx & 127;
    int t = idx >> 7;
    int qp = t & (Ss - 1);
    int zz = t >> 11;
    int b = zz >> 3, h = zz & 7;
    int row = b * Ss + qp;
    float v = (d < 64) ? kv[row * 2560 + h * 64 + d] : kr[row * 64 + (d - 64)];
    __nv_bfloat16 hh = __float2bfloat16(v);
    kh[idx] = hh;
    kl[idx] = __float2bfloat16(v - __bfloat162float(hh));
}

__global__ void softmax_kernel(float* __restrict__ sc)
{
    float* p = sc + (long long)blockIdx.x * 2048;
    int tid = threadIdx.x;
    float v[8];
#pragma unroll
    for (int i = 0; i < 8; i++) v[i] = p[tid + 256 * i];
    float m = v[0];
#pragma unroll
    for (int i = 1; i < 8; i++) m = fmaxf(m, v[i]);
#pragma unroll
    for (int o = 16; o; o >>= 1) m = fmaxf(m, __shfl_xor_sync(0xffffffffu, m, o));
    __shared__ float redm[8];
    int lane = tid & 31, w = tid >> 5;
    if (lane == 0) redm[w] = m;
    __syncthreads();
    m = redm[0];
#pragma unroll
    for (int i = 1; i < 8; i++) m = fmaxf(m, redm[i]);
    float sum = 0.f;
#pragma unroll
    for (int i = 0; i < 8; i++) { v[i] = __expf(v[i] - m); sum += v[i]; }
#pragma unroll
    for (int o = 16; o; o >>= 1) sum += __shfl_xor_sync(0xffffffffu, sum, o);
    __shared__ float reds[8];
    if (lane == 0) reds[w] = sum;
    __syncthreads();
    sum = 0.f;
#pragma unroll
    for (int i = 0; i < 8; i++) sum += reds[i];
    float inv = 1.f / sum;
#pragma unroll
    for (int i = 0; i < 8; i++) p[tid + 256 * i] = v[i] * inv;
}

// ================= launch =================
extern "C" void kernel_launch(void* const* d_in, const int* in_sizes, int n_in,
                              void* d_out, int out_size)
{
    const float* x         = (const float*)d_in[0];
    const int*   pos       = (const int*)  d_in[1];
    const float* w_dq_w    = (const float*)d_in[2];
    const float* w_dq_b    = (const float*)d_in[3];
    const float* q_norm_w  = (const float*)d_in[4];
    const float* w_uq_qr_w = (const float*)d_in[5];
    const float* w_uq_qr_b = (const float*)d_in[6];
    const float* w_dkv_w   = (const float*)d_in[7];
    const float* w_dkv_b   = (const float*)d_in[8];
    const float* kv_norm_w = (const float*)d_in[9];
    const float* w_ukuv_w  = (const float*)d_in[10];
    const float* w_ukuv_b  = (const float*)d_in[11];
    const float* w_o_w     = (const float*)d_in[12];
    const float* w_o_b     = (const float*)d_in[13];
    float* out = (float*)d_out;

    float *p_cq, *p_q, *p_ckvkr, *p_ckv, *p_kr, *p_kv, *p_qs, *p_sc, *p_attn;
    __nv_bfloat16 *p_ksh, *p_ksl, *p_vth, *p_vtl;
    __nv_bfloat16 *p_wdqh, *p_wdql, *p_wuqh, *p_wuql, *p_wdkvh, *p_wdkvl;
    __nv_bfloat16 *p_wukuvh, *p_wukuvl, *p_woh, *p_wol;
    cudaGetSymbolAddress((void**)&p_cq,    g_cq);
    cudaGetSymbolAddress((void**)&p_q,     g_q);
    cudaGetSymbolAddress((void**)&p_ckvkr, g_ckvkr);
    cudaGetSymbolAddress((void**)&p_ckv,   g_ckv);
    cudaGetSymbolAddress((void**)&p_kr,    g_kr);
    cudaGetSymbolAddress((void**)&p_kv,    g_kv);
    cudaGetSymbolAddress((void**)&p_qs,    g_qs);
    cudaGetSymbolAddress((void**)&p_sc,    g_sc);
    cudaGetSymbolAddress((void**)&p_attn,  g_attn);
    cudaGetSymbolAddress((void**)&p_ksh,   g_ks_h);
    cudaGetSymbolAddress((void**)&p_ksl,   g_ks_l);
    cudaGetSymbolAddress((void**)&p_vth,   g_vt_h);
    cudaGetSymbolAddress((void**)&p_vtl,   g_vt_l);
    cudaGetSymbolAddress((void**)&p_wdqh,  g_wdq_h);
    cudaGetSymbolAddress((void**)&p_wdql,  g_wdq_l);
    cudaGetSymbolAddress((void**)&p_wuqh,  g_wuq_h);
    cudaGetSymbolAddress((void**)&p_wuql,  g_wuq_l);
    cudaGetSymbolAddress((void**)&p_wdkvh, g_wdkv_h);
    cudaGetSymbolAddress((void**)&p_wdkvl, g_wdkv_l);
    cudaGetSymbolAddress((void**)&p_wukuvh, g_wukuv_h);
    cudaGetSymbolAddress((void**)&p_wukuvl, g_wukuv_l);
    cudaGetSymbolAddress((void**)&p_woh,   g_wo_h);
    cudaGetSymbolAddress((void**)&p_wol,   g_wo_l);

    cudaFuncSetAttribute(hgemm2_kernel<0>, cudaFuncAttributeMaxDynamicSharedMemorySize,
                         GEMM_SMEM);
    cudaFuncSetAttribute(hgemm2_kernel<1>, cudaFuncAttributeMaxDynamicSharedMemorySize,
                         GEMM_SMEM);

    dim3 tb(32, 8);

    // ---- weight transpose + split ----
    transpose_split_kernel<<<dim3(4, 32),  tb>>>(w_dq_w,    1024, 128,  p_wdqh, p_wdql);
    transpose_split_kernel<<<dim3(32, 4),  tb>>>(w_uq_qr_w, 128, 1024,  p_wuqh, p_wuql);
    transpose_split_kernel<<<dim3(6, 32),  tb>>>(w_dkv_w,   1024, 192,  p_wdkvh, p_wdkvl);
    transpose_split_kernel<<<dim3(80, 4),  tb>>>(w_ukuv_w,  128, 2560,  p_wukuvh, p_wukuvl);
    transpose_split_kernel<<<dim3(32, 64), tb>>>(w_o_w,     2048, 1024, p_woh, p_wol);

    // 1) cq = x @ w_dq + b
    hgemm2_kernel<0><<<dim3(1, 32, 1), 256, GEMM_SMEM>>>(
        x, 1024, 0, p_wdqh, p_wdql, 1024, 0, w_dq_b, p_cq, 128, 0, 128, 1024, 1.f);
    // 2) rmsnorm
    rmsnorm128_kernel<<<MTOK, 128>>>(p_cq, q_norm_w);
    // 3) q = cq @ w_uq + b
    hgemm2_kernel<0><<<dim3(8, 32, 1), 256, GEMM_SMEM>>>(
        p_cq, 128, 0, p_wuqh, p_wuql, 128, 0, w_uq_qr_b, p_q, 1024, 0, 1024, 128, 1.f);
    // 4) ckv_kr = x @ w_dkv + b
    hgemm2_kernel<0><<<dim3(2, 32, 1), 256, GEMM_SMEM>>>(
        x, 1024, 0, p_wdkvh, p_wdkvl, 1024, 0, w_dkv_b, p_ckvkr, 192, 0, 192, 1024, 1.f);
    // 5) rmsnorm(ckv) + rope(k_rope)
    post_ckvkr_kernel<<<MTOK, 128>>>(p_ckvkr, kv_norm_w, pos, p_ckv, p_kr);
    // 6) kv = ckv @ w_ukuv + b
    hgemm2_kernel<0><<<dim3(20, 32, 1), 256, GEMM_SMEM>>>(
        p_ckv, 128, 0, p_wukuvh, p_wukuvl, 128, 0, w_ukuv_b, p_kv, 2560, 0, 2560, 128, 1.f);
    // 7) build q states (fp32), k states (split), V^T (split)
    build_q_kernel<<<(NBATCH * Ss * 128) / 256, 256>>>(p_q, pos, p_qs);
    build_k_split_kernel<<<(NBATCH * Ss * 128) / 256, 256>>>(p_kv, p_kr, p_ksh, p_ksl);
    build_vT_split_kernel<<<dim3(64, 8, NBATCH), tb>>>(p_kv, p_vth, p_vtl);
    // 8) scores = scale * Q @ K^T
    hgemm2_kernel<0><<<dim3(16, 16, NBATCH), 256, GEMM_SMEM>>>(
        p_qs, 128, (long long)Ss * 128,
        p_ksh, p_ksl, 128, (long long)Ss * 128,
        nullptr,
        p_sc, Ss, (long long)Ss * Ss,
        Ss, 128, SCALE);
    // 9) softmax rows
    softmax_kernel<<<NBATCH * Ss, 256>>>(p_sc);
    // 10) attn = P @ V  (write directly into permuted [B*S][H*256])
    hgemm2_kernel<1><<<dim3(2, 16, NBATCH), 256, GEMM_SMEM>>>(
        p_sc, Ss, (long long)Ss * Ss,
        p_vth, p_vtl, Ss, (long long)256 * Ss,
        nullptr,
        p_attn, 0, 0,
        256, Ss, 1.f);
    // 11) out = attn @ w_o + b
    hgemm2_kernel<0><<<dim3(8, 32, 1), 256, GEMM_SMEM>>>(
        p_attn, 2048, 0, p_woh, p_wol, 2048, 0, w_o_b, out, 1024, 0, 1024, 2048, 1.f);
}